// round 13
// baseline (speedup 1.0000x reference)
#include <cuda_runtime.h>
#include <cuda_fp16.h>
#include <cstdint>
#include <cstddef>

#define I_DIM 512
#define O_DIM 512
#define KDIM  4096          // I_DIM * 8 degrees
#define TILE_M 128
#define TILE_N 128
#define KC     64           // K elems per chunk (8 i's x 8 degrees)
#define NCHUNK (KDIM / KC)  // 64
#define THREADS 256
#define PITCH  144          // 64 halves (128B) + 16B pad; 36 words -> +4 banks/row

#define COEF_SCALE   1024.0f
#define OUT_SCALE    (1.0f / 1024.0f)

// Transposed, scaled fp16 coefficients: Wh[o][k], k = i*8 + d
__device__ __align__(16) __half g_Wh[(size_t)O_DIM * KDIM];

// ---------------- helpers ----------------
__device__ __forceinline__ uint32_t smem_u32(const void* p) {
    uint32_t a;
    asm("{ .reg .u64 t; cvta.to.shared.u64 t, %1; cvt.u32.u64 %0, t; }"
        : "=r"(a) : "l"(p));
    return a;
}

__device__ __forceinline__ void sts128(uint32_t a, uint32_t v0, uint32_t v1,
                                       uint32_t v2, uint32_t v3) {
    asm volatile("st.shared.v4.b32 [%0], {%1,%2,%3,%4};"
                 :: "r"(a), "r"(v0), "r"(v1), "r"(v2), "r"(v3) : "memory");
}

__device__ __forceinline__ void ldsm4(uint32_t* r, uint32_t addr) {
    asm volatile("ldmatrix.sync.aligned.m8n8.x4.shared.b16 {%0,%1,%2,%3}, [%4];"
                 : "=r"(r[0]), "=r"(r[1]), "=r"(r[2]), "=r"(r[3]) : "r"(addr));
}

// m16n8k16 fp16 MMA with **fp16 accumulators** (2 packed b32 regs)
__device__ __forceinline__ void mma16h(uint32_t* c, const uint32_t* a,
                                       const uint32_t* b) {
    asm volatile(
        "mma.sync.aligned.m16n8k16.row.col.f16.f16.f16.f16 "
        "{%0,%1}, {%2,%3,%4,%5}, {%6,%7}, {%0,%1};"
        : "+r"(c[0]), "+r"(c[1])
        : "r"(a[0]), "r"(a[1]), "r"(a[2]), "r"(a[3]), "r"(b[0]), "r"(b[1]));
}

__device__ __forceinline__ uint32_t pack_h2(float lo, float hi) {
    __half2 h = __floats2half2_rn(lo, hi);
    return *reinterpret_cast<uint32_t*>(&h);
}

// accurate-enough tanh: 1 - 2/(exp(2x)+1); MUFU-based, err ~1e-6
__device__ __forceinline__ float fast_tanh(float x) {
    float e = __expf(2.0f * x);
    return 1.0f - __fdividef(2.0f, e + 1.0f);
}

// ---------------- kernel 0: transpose + scale coeffs to fp16 ----------------
__global__ void prep_kernel(const float* __restrict__ coeffs) {
    int idx = blockIdx.x * blockDim.x + threadIdx.x;   // coalesced read
    int i = idx >> 12;
    int o = (idx >> 3) & 511;
    int d = idx & 7;
    g_Wh[((size_t)o << 12) + (i << 3) + d] =
        __float2half_rn(coeffs[idx] * COEF_SCALE);
}

// ---------------- kernel 1: fused poly + fp16 mma (f16 acc) GEMM -----------
// A stage = 128*144 = 18432 B, B stage = 18432 B; double buffered
#define ST_SIZE  18432u
#define SMEM_BYTES (4 * 18432)   // 73728

__global__ void __launch_bounds__(THREADS, 1)
gegen_kernel(const float* __restrict__ x, float* __restrict__ out) {
    extern __shared__ __align__(16) char smem[];
    const uint32_t sb = smem_u32(smem);
    const int tid  = threadIdx.x;
    const int lane = tid & 31;
    const int wid  = tid >> 5;
    const int b0 = blockIdx.x * TILE_M;
    const int o0 = blockIdx.y * TILE_N;
    const int wm = (wid & 3) * 32;     // 4 warps in M
    const int wn = (wid >> 2) * 64;    // 2 warps in N

    uint32_t aBase[2], bBase[2];
#pragma unroll
    for (int s = 0; s < 2; s++) {
        aBase[s] = sb + s * ST_SIZE;
        bBase[s] = sb + 2 * ST_SIZE + s * ST_SIZE;
    }

    // fp16 packed accumulators (per-chunk window) + fp32 shadow accumulators
    uint32_t acc16[2][8][2];
    float    acc32[2][8][4];
#pragma unroll
    for (int mf = 0; mf < 2; mf++)
#pragma unroll
        for (int nf = 0; nf < 8; nf++) {
            acc16[mf][nf][0] = 0u; acc16[mf][nf][1] = 0u;
#pragma unroll
            for (int j = 0; j < 4; j++) acc32[mf][nf][j] = 0.0f;
        }

    // ---- ldmatrix per-lane offsets (relative to stage base) ----
    const int a_r = lane & 15;
    const int a_c = (lane >> 4) * 16;
    uint32_t aoff[2];
#pragma unroll
    for (int mf = 0; mf < 2; mf++)
        aoff[mf] = (uint32_t)(wm + mf * 16 + a_r) * PITCH + a_c;
    const int b_r = (lane & 7) + ((lane >> 4) & 1) * 8;
    const int b_c = ((lane >> 3) & 1) * 16;
    uint32_t boff[4];
#pragma unroll
    for (int p = 0; p < 4; p++)
        boff[p] = (uint32_t)(wn + p * 16 + b_r) * PITCH + b_c;

    // ---- producer bases: 2 threads per row; half covers 4 i's (=32 k) ----
    const int prow = tid >> 1;
    const int half = tid & 1;
    const float* xrow = x + (size_t)(b0 + prow) * I_DIM + half * 4;
    const __half* wrow = g_Wh + ((size_t)(o0 + prow) << 12) + half * 32;
    const uint32_t a_sts = prow * PITCH + half * 64;
    const uint32_t b_sts = prow * PITCH + half * 64;

    auto cp_b = [&](int c, uint32_t bBuf) {
        const __half* src = wrow + c * KC;
#pragma unroll
        for (int j = 0; j < 4; j++) {
            asm volatile("cp.async.cg.shared.global [%0], [%1], 16;"
                         :: "r"(bBuf + b_sts + j * 16), "l"(src + j * 8)
                         : "memory");
        }
        asm volatile("cp.async.commit_group;" ::: "memory");
    };

    auto produce_a = [&](uint32_t aBuf, const float4& xv) {
        const float xs[4] = {xv.x, xv.y, xv.z, xv.w};
#pragma unroll
        for (int ii = 0; ii < 4; ii++) {
            float t  = fast_tanh(xs[ii]);
            float t2 = t + t;
            float c0 = 1.0f, c1 = t2;
            float c2 = fmaf(t2, c1, -c0);
            float c3 = fmaf(t2, c2, -c1);
            float c4 = fmaf(t2, c3, -c2);
            float c5 = fmaf(t2, c4, -c3);
            float c6 = fmaf(t2, c5, -c4);
            float c7 = fmaf(t2, c6, -c5);
            sts128(aBuf + a_sts + ii * 16,
                   pack_h2(c0, c1), pack_h2(c2, c3),
                   pack_h2(c4, c5), pack_h2(c6, c7));
        }
    };

    auto consume = [&](uint32_t aBuf, uint32_t bBuf) {
#pragma unroll
        for (int ks = 0; ks < 4; ks++) {
            const uint32_t koff = ks * 32;
            uint32_t a[2][4], b[4][4];
#pragma unroll
            for (int mf = 0; mf < 2; mf++) ldsm4(a[mf], aBuf + aoff[mf] + koff);
#pragma unroll
            for (int p = 0; p < 4; p++)   ldsm4(b[p], bBuf + boff[p] + koff);
#pragma unroll
            for (int mf = 0; mf < 2; mf++)
#pragma unroll
                for (int nf = 0; nf < 8; nf++)
                    mma16h(acc16[mf][nf], a[mf], &b[nf >> 1][(nf & 1) * 2]);
        }
    };

    // drain fp16 window into fp32 shadow; reset window
    auto drain = [&]() {
#pragma unroll
        for (int mf = 0; mf < 2; mf++)
#pragma unroll
            for (int nf = 0; nf < 8; nf++) {
                float2 v0 = __half22float2(
                    *reinterpret_cast<__half2*>(&acc16[mf][nf][0]));
                float2 v1 = __half22float2(
                    *reinterpret_cast<__half2*>(&acc16[mf][nf][1]));
                acc32[mf][nf][0] += v0.x;
                acc32[mf][nf][1] += v0.y;
                acc32[mf][nf][2] += v1.x;
                acc32[mf][nf][3] += v1.y;
                acc16[mf][nf][0] = 0u;
                acc16[mf][nf][1] = 0u;
            }
    };

    // ---- prologue: fill chunk 0 ----
    float4 xv = *reinterpret_cast<const float4*>(xrow);
    cp_b(0, bBase[0]);
    produce_a(aBase[0], xv);
    xv = *reinterpret_cast<const float4*>(xrow + 8);     // chunk 1 x's

    // ---- main loop: sync -> cp_b(c+1) -> consume(c)+drain -> produce(c+1) --
#pragma unroll 1
    for (int c = 0; c < NCHUNK; c++) {
        asm volatile("cp.async.wait_group 0;" ::: "memory");
        __syncthreads();   // chunk c visible; buf (c+1)&1 free

        const int cur = c & 1, nxt = cur ^ 1;
        if (c + 1 < NCHUNK) cp_b(c + 1, bBase[nxt]);

        consume(aBase[cur], bBase[cur]);

        if (c + 1 < NCHUNK) {
            produce_a(aBase[nxt], xv);
            if (c + 2 < NCHUNK)
                xv = *reinterpret_cast<const float4*>(xrow + (c + 2) * 8);
        }
        drain();           // fp16 window (K=64) -> fp32 shadow
    }

    // ---- epilogue: scale back and store ----
#pragma unroll
    for (int mf = 0; mf < 2; mf++) {
        const int rbase = b0 + wm + mf * 16 + (lane >> 2);
#pragma unroll
        for (int h = 0; h < 2; h++) {
            float* op = out + (size_t)(rbase + h * 8) * O_DIM
                            + o0 + wn + (lane & 3) * 2;
#pragma unroll
            for (int nf = 0; nf < 8; nf++) {
                float2 v;
                v.x = acc32[mf][nf][h * 2]     * OUT_SCALE;
                v.y = acc32[mf][nf][h * 2 + 1] * OUT_SCALE;
                *reinterpret_cast<float2*>(op + nf * 8) = v;
            }
        }
    }
}

// ---------------- launch ----------------
extern "C" void kernel_launch(void* const* d_in, const int* in_sizes, int n_in,
                              void* d_out, int out_size) {
    const float* x      = (const float*)d_in[0];
    const float* coeffs = (const float*)d_in[1];
    float* out          = (float*)d_out;

    const int B = in_sizes[0] / I_DIM;   // 16384

    prep_kernel<<<(I_DIM * O_DIM * 8) / 256, 256>>>(coeffs);

    cudaFuncSetAttribute(gegen_kernel,
                         cudaFuncAttributeMaxDynamicSharedMemorySize, SMEM_BYTES);

    dim3 grid(B / TILE_M, O_DIM / TILE_N);
    gegen_kernel<<<grid, THREADS, SMEM_BYTES>>>(x, out);
}

// round 14
// speedup vs baseline: 1.3404x; 1.3404x over previous
#include <cuda_runtime.h>
#include <cuda_fp16.h>
#include <cstdint>
#include <cstddef>

#define I_DIM 512
#define O_DIM 512
#define KDIM  3584          // I_DIM * 7 degrees (d=0 folded into bias)
#define TILE_M 256
#define TILE_N 128
#define KC     112          // 16 i's x 7 degrees; 7 k16-steps
#define NCHUNK (KDIM / KC)  // 32
#define THREADS 256
#define PITCH  240          // 112 halves (224B) + 16B pad; 60 words -> +28 banks/row

#define COEF_SCALE   1024.0f
#define OUT_SCALE    (1.0f / 1024.0f)

// Repacked, scaled fp16 coefficients: Wh[o][k'], k' = i*7 + (d-1)
__device__ __align__(16) __half g_Wh[(size_t)O_DIM * KDIM];
// Scaled bias: g_bias[o] = 1024 * sum_i coeffs[i][o][0]
__device__ __align__(16) float g_bias[O_DIM];

// ---------------- helpers ----------------
__device__ __forceinline__ uint32_t smem_u32(const void* p) {
    uint32_t a;
    asm("{ .reg .u64 t; cvta.to.shared.u64 t, %1; cvt.u32.u64 %0, t; }"
        : "=r"(a) : "l"(p));
    return a;
}

__device__ __forceinline__ void sts64(uint32_t a, uint32_t v0, uint32_t v1) {
    asm volatile("st.shared.v2.b32 [%0], {%1,%2};"
                 :: "r"(a), "r"(v0), "r"(v1) : "memory");
}

__device__ __forceinline__ void ldsm4(uint32_t* r, uint32_t addr) {
    asm volatile("ldmatrix.sync.aligned.m8n8.x4.shared.b16 {%0,%1,%2,%3}, [%4];"
                 : "=r"(r[0]), "=r"(r[1]), "=r"(r[2]), "=r"(r[3]) : "r"(addr));
}

// m16n8k16 fp16 MMA, f32 accumulate
__device__ __forceinline__ void mma16(float* c, const uint32_t* a, const uint32_t* b) {
    asm volatile(
        "mma.sync.aligned.m16n8k16.row.col.f32.f16.f16.f32 "
        "{%0,%1,%2,%3}, {%4,%5,%6,%7}, {%8,%9}, {%0,%1,%2,%3};"
        : "+f"(c[0]), "+f"(c[1]), "+f"(c[2]), "+f"(c[3])
        : "r"(a[0]), "r"(a[1]), "r"(a[2]), "r"(a[3]), "r"(b[0]), "r"(b[1]));
}

__device__ __forceinline__ uint32_t pack_h2(float lo, float hi) {
    __half2 h = __floats2half2_rn(lo, hi);
    return *reinterpret_cast<uint32_t*>(&h);
}

// accurate-enough tanh: 1 - 2/(exp(2x)+1); MUFU-based, err ~1e-6
__device__ __forceinline__ float fast_tanh(float x) {
    float e = __expf(2.0f * x);
    return 1.0f - __fdividef(2.0f, e + 1.0f);
}

// ---------------- kernel 0: repack + scale coeffs (d>=1) to fp16 -----------
__global__ void prep_kernel(const float* __restrict__ coeffs) {
    int idx = blockIdx.x * blockDim.x + threadIdx.x;   // coalesced read, (i,o,d)
    int i = idx >> 12;
    int o = (idx >> 3) & 511;
    int d = idx & 7;
    if (d > 0) {
        g_Wh[(size_t)o * KDIM + i * 7 + (d - 1)] =
            __float2half_rn(coeffs[idx] * COEF_SCALE);
    }
}

// ---------------- kernel 1: bias[o] = 1024 * sum_i coeffs[i][o][0] ---------
__global__ void bias_kernel(const float* __restrict__ coeffs) {
    int o = blockIdx.x * blockDim.x + threadIdx.x;     // 512 threads
    float s = 0.0f;
    for (int i = 0; i < I_DIM; i++)
        s += coeffs[(((size_t)i << 9) + o) << 3];      // (i,o,0)
    g_bias[o] = s * COEF_SCALE;
}

// ---------------- kernel 2: fused poly + fp16 mma GEMM (K=3584) ------------
// A stage = 256*240 = 61440 B, B stage = 128*240 = 30720 B; double buffered
#define ST_A 61440u
#define ST_B 30720u
#define SMEM_BYTES (2 * (61440 + 30720))   // 184320

__global__ void __launch_bounds__(THREADS, 1)
gegen_kernel(const float* __restrict__ x, float* __restrict__ out) {
    extern __shared__ __align__(16) char smem[];
    const uint32_t sb = smem_u32(smem);
    const int tid  = threadIdx.x;
    const int lane = tid & 31;
    const int wid  = tid >> 5;
    const int b0 = blockIdx.x * TILE_M;
    const int o0 = blockIdx.y * TILE_N;
    const int wm = (wid & 3) * 64;     // 4 warps in M
    const int wn = (wid >> 2) * 64;    // 2 warps in N

    uint32_t aBase[2], bBase[2];
#pragma unroll
    for (int s = 0; s < 2; s++) {
        aBase[s] = sb + s * ST_A;
        bBase[s] = sb + 2 * ST_A + s * ST_B;
    }

    // ---- accumulators initialized with bias ----
    float acc[4][8][4];
#pragma unroll
    for (int nf = 0; nf < 8; nf++) {
        const float* bp = g_bias + o0 + wn + nf * 8 + (lane & 3) * 2;
        float bx = bp[0], by = bp[1];
#pragma unroll
        for (int mf = 0; mf < 4; mf++) {
            acc[mf][nf][0] = bx; acc[mf][nf][1] = by;
            acc[mf][nf][2] = bx; acc[mf][nf][3] = by;
        }
    }

    // ---- ldmatrix per-lane offsets (relative to stage base) ----
    const int a_r = lane & 15;
    const int a_c = (lane >> 4) * 16;
    uint32_t aoff[4];
#pragma unroll
    for (int mf = 0; mf < 4; mf++)
        aoff[mf] = (uint32_t)(wm + mf * 16 + a_r) * PITCH + a_c;
    const int b_r = (lane & 7) + ((lane >> 4) & 1) * 8;
    const int b_c = ((lane >> 3) & 1) * 16;
    uint32_t boff[4];
#pragma unroll
    for (int p = 0; p < 4; p++)
        boff[p] = (uint32_t)(wn + p * 16 + b_r) * PITCH + b_c;

    // ---- producer bases ----
    // A: one thread per m-row; chunk c covers i in [16c, 16c+16)
    const float* xrow = x + (size_t)(b0 + tid) * I_DIM;
    const uint32_t a_sts = tid * PITCH;
    // B: 2 threads per o-row; half covers 56 halves (112 B)
    const __half* wrow = g_Wh + (size_t)(o0 + (tid >> 1)) * KDIM + (tid & 1) * 56;
    const uint32_t b_sts = (tid >> 1) * PITCH + (tid & 1) * 112;

    auto cp_b = [&](int c, uint32_t bBuf) {
        const __half* src = wrow + c * KC;
#pragma unroll
        for (int j = 0; j < 7; j++) {
            asm volatile("cp.async.cg.shared.global [%0], [%1], 16;"
                         :: "r"(bBuf + b_sts + j * 16), "l"(src + j * 8)
                         : "memory");
        }
        asm volatile("cp.async.commit_group;" ::: "memory");
    };

    // produce A for chunk: 16 polys (c1..c7 each), packed across poly
    // boundaries: 4-poly unit = 28 halves = 14 u32 = 7 sts64 (8B aligned)
    auto produce_a = [&](uint32_t aBuf, const float4* xv) {
#pragma unroll
        for (int g2 = 0; g2 < 4; g2++) {           // 4 units of 4 polys
            const float xs[4] = {xv[g2].x, xv[g2].y, xv[g2].z, xv[g2].w};
            float C[4][7];
#pragma unroll
            for (int p = 0; p < 4; p++) {
                float t  = fast_tanh(xs[p]);
                float t2 = t + t;
                C[p][0] = t2;
                C[p][1] = fmaf(t2, C[p][0], -1.0f);
#pragma unroll
                for (int n = 2; n < 7; n++)
                    C[p][n] = fmaf(t2, C[p][n - 1], -C[p][n - 2]);
            }
            const uint32_t base = aBuf + a_sts + g2 * 56;
            // u0..u13 packing (poly-boundary-crossing pairs)
            sts64(base +  0, pack_h2(C[0][0], C[0][1]), pack_h2(C[0][2], C[0][3]));
            sts64(base +  8, pack_h2(C[0][4], C[0][5]), pack_h2(C[0][6], C[1][0]));
            sts64(base + 16, pack_h2(C[1][1], C[1][2]), pack_h2(C[1][3], C[1][4]));
            sts64(base + 24, pack_h2(C[1][5], C[1][6]), pack_h2(C[2][0], C[2][1]));
            sts64(base + 32, pack_h2(C[2][2], C[2][3]), pack_h2(C[2][4], C[2][5]));
            sts64(base + 40, pack_h2(C[2][6], C[3][0]), pack_h2(C[3][1], C[3][2]));
            sts64(base + 48, pack_h2(C[3][3], C[3][4]), pack_h2(C[3][5], C[3][6]));
        }
    };

    auto consume = [&](uint32_t aBuf, uint32_t bBuf) {
#pragma unroll
        for (int ks = 0; ks < 7; ks++) {
            const uint32_t koff = ks * 32;
            uint32_t a[4][4], b[4][4];
#pragma unroll
            for (int mf = 0; mf < 4; mf++) ldsm4(a[mf], aBuf + aoff[mf] + koff);
#pragma unroll
            for (int p = 0; p < 4; p++)   ldsm4(b[p], bBuf + boff[p] + koff);
#pragma unroll
            for (int mf = 0; mf < 4; mf++)
#pragma unroll
                for (int nf = 0; nf < 8; nf++)
                    mma16(acc[mf][nf], a[mf], &b[nf >> 1][(nf & 1) * 2]);
        }
    };

    // ---- prologue: fill chunk 0 ----
    float4 xv[4];
#pragma unroll
    for (int q = 0; q < 4; q++)
        xv[q] = *reinterpret_cast<const float4*>(xrow + q * 4);
    cp_b(0, bBase[0]);
    produce_a(aBase[0], xv);
#pragma unroll
    for (int q = 0; q < 4; q++)                       // chunk 1 x's
        xv[q] = *reinterpret_cast<const float4*>(xrow + 16 + q * 4);

    // ---- main loop: sync -> cp_b(c+1) -> consume(c) -> produce_a(c+1) ----
#pragma unroll 1
    for (int c = 0; c < NCHUNK; c++) {
        asm volatile("cp.async.wait_group 0;" ::: "memory");
        __syncthreads();   // chunk c visible; buf (c+1)&1 free

        const int cur = c & 1, nxt = cur ^ 1;
        if (c + 1 < NCHUNK) cp_b(c + 1, bBase[nxt]);

        consume(aBase[cur], bBase[cur]);

        if (c + 1 < NCHUNK) {
            produce_a(aBase[nxt], xv);
            if (c + 2 < NCHUNK) {
#pragma unroll
                for (int q = 0; q < 4; q++)
                    xv[q] = *reinterpret_cast<const float4*>(
                        xrow + (c + 2) * 16 + q * 4);
            }
        }
    }

    // ---- epilogue: scale back and store (bias already in acc) ----
#pragma unroll
    for (int mf = 0; mf < 4; mf++) {
        const int rbase = b0 + wm + mf * 16 + (lane >> 2);
#pragma unroll
        for (int h = 0; h < 2; h++) {
            float* op = out + (size_t)(rbase + h * 8) * O_DIM
                            + o0 + wn + (lane & 3) * 2;
#pragma unroll
            for (int nf = 0; nf < 8; nf++) {
                float2 v;
                v.x = acc[mf][nf][h * 2]     * OUT_SCALE;
                v.y = acc[mf][nf][h * 2 + 1] * OUT_SCALE;
                *reinterpret_cast<float2*>(op + nf * 8) = v;
            }
        }
    }
}

// ---------------- launch ----------------
extern "C" void kernel_launch(void* const* d_in, const int* in_sizes, int n_in,
                              void* d_out, int out_size) {
    const float* x      = (const float*)d_in[0];
    const float* coeffs = (const float*)d_in[1];
    float* out          = (float*)d_out;

    const int B = in_sizes[0] / I_DIM;   // 16384

    prep_kernel<<<(I_DIM * O_DIM * 8) / 256, 256>>>(coeffs);
    bias_kernel<<<2, 256>>>(coeffs);

    cudaFuncSetAttribute(gegen_kernel,
                         cudaFuncAttributeMaxDynamicSharedMemorySize, SMEM_BYTES);

    dim3 grid(B / TILE_M, O_DIM / TILE_N);
    gegen_kernel<<<grid, THREADS, SMEM_BYTES>>>(x, out);
}